// round 8
// baseline (speedup 1.0000x reference)
#include <cuda_runtime.h>
#include <cstdint>
#include <math.h>

#define IN_SIZE  128
#define OUT_SIZE 128
#define BATCH    1024
#define N_SUB    (IN_SIZE * OUT_SIZE)

// Per-subnet flat PWL table (292 floats, 1168 B):
//  [0..127]   Eytzinger(BFS) tree of sorted kinks, slot 0 unused,
//             padded with SENT beyond the M real kinks (M <= 80)
//  [128..208] A[81]  segment slopes
//  [209..289] B[81]  segment intercepts
//  [290..291] pad (keeps 16B-aligned stride)
#define TAB  292
#define SENT 3.0e38f
#define BIG  1.0e37f

__device__ float g_xT[IN_SIZE * BATCH];   // transposed x
__device__ float g_tab[N_SUB * TAB];      // 19.1 MB static scratch

// ---------- xt: transpose x, zero out, init all tree slots to SENT ----------
__global__ void xt_kernel(const float* __restrict__ x, float* __restrict__ out) {
    __shared__ float t[32][33];
    const int i0 = blockIdx.x * 32;
    const int bx = blockIdx.y * 32;
    const int tx = threadIdx.x, ty = threadIdx.y;  // 32 x 8
#pragma unroll
    for (int r = 0; r < 32; r += 8)
        t[ty + r][tx] = x[(bx + ty + r) * IN_SIZE + i0 + tx];
    __syncthreads();
#pragma unroll
    for (int r = 0; r < 32; r += 8)
        g_xT[(i0 + ty + r) * BATCH + bx + tx] = t[tx][ty + r];

    // flat id 0..32767 over the (4 x 32) x 256 launch
    const int gid = (blockIdx.y * 4 + blockIdx.x) * 256 + ty * 32 + tx;
    reinterpret_cast<float4*>(out)[gid] = make_float4(0.f, 0.f, 0.f, 0.f);

    // init the 16384 x 128 tree region to SENT (coalesced)
#pragma unroll
    for (int j = 0; j < 64; j++) {
        const int fidx = j * 32768 + gid;            // 0 .. 2097151
        g_tab[(fidx >> 7) * TAB + (fidx & 127)] = SENT;
    }
}

// ---------- helpers ----------
__device__ __forceinline__ void sort8(float* v) {
#pragma unroll
    for (int p = 0; p < 8; p++)
#pragma unroll
        for (int k = 0; k < 7; k++)
            if ((k & 1) == (p & 1)) {
                const float lo = fminf(v[k], v[k + 1]);
                const float hi = fmaxf(v[k], v[k + 1]);
                v[k] = lo; v[k + 1] = hi;
            }
}

// ---------- prep: build flat PWL table per subnet (1 thread / subnet) -------
__global__ void __launch_bounds__(128) prep_kernel(
    const float* __restrict__ W1, const float* __restrict__ b1,
    const float* __restrict__ W2, const float* __restrict__ b2,
    const float* __restrict__ W3, const float* __restrict__ b3) {
    const int n = blockIdx.x * 128 + threadIdx.x;

    float w1[8], c1[8], c2[8], w3r[8], w2[64];
#pragma unroll
    for (int k = 0; k < 8; k++) {
        w1[k]  = __ldg(W1 + n * 8 + k);
        c1[k]  = __ldg(b1 + n * 8 + k);
        c2[k]  = __ldg(b2 + n * 8 + k);
        w3r[k] = __ldg(W3 + n * 8 + k);
    }
#pragma unroll
    for (int e = 0; e < 64; e++) w2[e] = __ldg(W2 + n * 64 + e);
    const float b3v = __ldg(b3 + n);

    // layer-1 thresholds, guarded + sorted (sentinel +SENT sorts to end)
    float tau[8];
#pragma unroll
    for (int k = 0; k < 8; k++) {
        float v = __fdividef(-c1[k], w1[k]);
        tau[k] = (fabsf(v) < BIG) ? v : SENT;
    }
    sort8(tau);

    float* dst = g_tab + (size_t)n * TAB;
    int r = 0;  // segment cursor == kinks emitted so far

#pragma unroll
    for (int s = 0; s < 9; s++) {
        const float loS = (s == 0) ? -SENT : tau[s - 1];
        const float hiS = (s == 8) ?  SENT : tau[s];

        // representative point of interval s (reachability-safe)
        float rep;
        if (s == 0)      rep = (tau[0] >= BIG) ? 0.0f
                                : tau[0] - (1.0f + 0.5f * fabsf(tau[0]));
        else if (s == 8) rep = tau[7] + (1.0f + 0.5f * fabsf(tau[7]));
        else             rep = 0.5f * tau[s - 1] + 0.5f * tau[s];

        // layer-2 affine coefs a_j, bb_j for this interval (registers)
        float a[8], bb[8];
#pragma unroll
        for (int j = 0; j < 8; j++) {
            float aa = 0.0f, bsum = c2[j];
#pragma unroll
            for (int k = 0; k < 8; k++) {
                const bool act = fmaf(w1[k], rep, c1[k]) > 0.0f;
                aa   = fmaf(w2[j * 8 + k], act ? w1[k] : 0.0f, aa);
                bsum = fmaf(w2[j * 8 + k], act ? c1[k] : 0.0f, bsum);
            }
            a[j] = aa; bb[j] = bsum;
        }

        // layer-2 hinge points strictly inside (loS, hiS), sorted
        float u[8];
#pragma unroll
        for (int j = 0; j < 8; j++) {
            const float uu = __fdividef(-bb[j], a[j]);
            const bool ok = (loS < uu) && (uu < hiS) && (fabsf(uu) < BIG);
            u[j] = ok ? uu : SENT;
        }
        sort8(u);

        // emit sub-segments of this interval
#pragma unroll
        for (int tt = 0; tt < 9; tt++) {
            const bool emit = (tt == 0) || (u[tt - 1] < BIG);
            if (emit) {
                const float sLo = (tt == 0) ? loS : u[tt - 1];
                const float sHi = (tt < 8 && u[tt] < BIG) ? u[tt] : hiS;

                float rep2;
                if (r == 0 && sHi >= BIG) rep2 = 0.0f;                 // no kinks
                else if (r == 0)          rep2 = sHi - (1.0f + 0.5f * fabsf(sHi));
                else if (sHi >= BIG)      rep2 = sLo + (1.0f + 0.5f * fabsf(sLo));
                else                      rep2 = 0.5f * sLo + 0.5f * sHi;

                float A = 0.0f, Bv = b3v;
#pragma unroll
                for (int j = 0; j < 8; j++) {
                    const bool act = fmaf(a[j], rep2, bb[j]) > 0.0f;
                    A  = fmaf(w3r[j], act ? a[j]  : 0.0f, A);
                    Bv = fmaf(w3r[j], act ? bb[j] : 0.0f, Bv);
                }
                dst[128 + r] = A;
                dst[209 + r] = Bv;

                if (sHi < BIG) {  // real kink (in-order index r) -> BFS slot
                    const int u1  = r + 1;
                    const int tz  = __ffs(u1) - 1;
                    const int bfs = (1 << (6 - tz)) + (u1 >> (tz + 1));
                    dst[bfs] = sHi;
                }
                r++;
            }
        }
    }
}

// ---------- eval: Eytzinger rank (7 steps) + 1 FMA per (subnet, batch) ------
#define O_PER_CTA 4
#define I_PER_CTA 8
#define SMEM_BYTES (O_PER_CTA * I_PER_CTA * TAB * 4)  // 37376

__global__ void __launch_bounds__(128, 6) eval_kernel(float* __restrict__ out) {
    extern __shared__ float sw[];
    const int obase = blockIdx.x * O_PER_CTA;
    const int bt    = blockIdx.y;
    const int ibase = blockIdx.z * I_PER_CTA;
    const int tid   = threadIdx.x;

    // stage 32 tables (73 float4 each), coalesced
    for (int idx = tid; idx < 32 * 73; idx += 128) {
        const int tI = idx / 73;
        const int e  = idx - tI * 73;
        const int li = tI >> 2, lo = tI & 3;
        const int nn = ((ibase + li) << 7) + obase + lo;
        reinterpret_cast<float4*>(sw)[tI * 73 + e] =
            __ldg(reinterpret_cast<const float4*>(g_tab + (size_t)nn * TAB) + e);
    }
    __syncthreads();

    const int b0 = bt * 512 + tid * 4;
    float4 xv = __ldg(reinterpret_cast<const float4*>(g_xT + ibase * BATCH + b0));

    float acc[O_PER_CTA][4];
#pragma unroll
    for (int lo = 0; lo < O_PER_CTA; lo++)
#pragma unroll
        for (int e = 0; e < 4; e++) acc[lo][e] = 0.f;

    for (int li = 0; li < I_PER_CTA; li++) {
        const int inx = ibase + ((li < I_PER_CTA - 1) ? (li + 1) : li);
        const float4 xnext =
            __ldg(reinterpret_cast<const float4*>(g_xT + inx * BATCH + b0));

#pragma unroll
        for (int lo = 0; lo < O_PER_CTA; lo++) {
            const float* sb = sw + (li * 4 + lo) * TAB;
            int i0 = 1, i1 = 1, i2 = 1, i3 = 1;
#pragma unroll
            for (int st = 0; st < 7; st++) {
                i0 = 2 * i0 + (xv.x > sb[i0]);
                i1 = 2 * i1 + (xv.y > sb[i1]);
                i2 = 2 * i2 + (xv.z > sb[i2]);
                i3 = 2 * i3 + (xv.w > sb[i3]);
            }
            i0 -= 128; i1 -= 128; i2 -= 128; i3 -= 128;
            acc[lo][0] = fmaf(sb[128 + i0], xv.x, acc[lo][0]) + sb[209 + i0];
            acc[lo][1] = fmaf(sb[128 + i1], xv.y, acc[lo][1]) + sb[209 + i1];
            acc[lo][2] = fmaf(sb[128 + i2], xv.z, acc[lo][2]) + sb[209 + i2];
            acc[lo][3] = fmaf(sb[128 + i3], xv.w, acc[lo][3]) + sb[209 + i3];
        }
        xv = xnext;
    }

#pragma unroll
    for (int lo = 0; lo < O_PER_CTA; lo++)
#pragma unroll
        for (int e = 0; e < 4; e++)
            atomicAdd(&out[(b0 + e) * OUT_SIZE + obase + lo], acc[lo][e]);
}

extern "C" void kernel_launch(void* const* d_in, const int* in_sizes, int n_in,
                              void* d_out, int out_size) {
    const float* x  = (const float*)d_in[0];
    const float* W1 = (const float*)d_in[1];
    const float* b1 = (const float*)d_in[2];
    const float* W2 = (const float*)d_in[3];
    const float* b2 = (const float*)d_in[4];
    const float* W3 = (const float*)d_in[5];
    const float* b3 = (const float*)d_in[6];
    float* out = (float*)d_out;

    cudaFuncSetAttribute(eval_kernel, cudaFuncAttributeMaxDynamicSharedMemorySize,
                         SMEM_BYTES);

    xt_kernel<<<dim3(IN_SIZE / 32, BATCH / 32), dim3(32, 8)>>>(x, out);
    prep_kernel<<<N_SUB / 128, 128>>>(W1, b1, W2, b2, W3, b3);
    eval_kernel<<<dim3(OUT_SIZE / O_PER_CTA, 2, IN_SIZE / I_PER_CTA), 128,
                  SMEM_BYTES>>>(out);
}

// round 9
// speedup vs baseline: 1.0931x; 1.0931x over previous
#include <cuda_runtime.h>
#include <cuda_fp16.h>
#include <cstdint>
#include <cstring>
#include <math.h>

#define IN_SIZE  128
#define OUT_SIZE 128
#define BATCH    1024
#define N_SUB    (IN_SIZE * OUT_SIZE)

// Per-subnet table: 256 floats (1024 B):
//  [0..3]          8 level-1 thresholds as 4x half2
//  per interval s (s=0..8), base = 4 + 28*s floats (112 B stride):
//     [+0..+3]     8 hinge positions u as 4x half2 (sorted, pad=+60000)
//     [+4..+21]    9 exact (A,B) fp32 pairs (sub-segment slope/intercept)
//     [+22..+27]   pad
//  => 4 + 9*28 = 256.  Interval base bank-quad (4+28s)%32 distinct except s=0/8.
#define TAB  256
#define SENT 3.0e38f
#define BIG  1.0e37f

__device__ float g_xT[IN_SIZE * BATCH];   // transposed x
__device__ float g_tab[N_SUB * TAB];      // 16.8 MB static scratch

// ---------------- xt: transpose x + zero the (poisoned) output ----------------
__global__ void xt_kernel(const float* __restrict__ x, float* __restrict__ out) {
    __shared__ float t[32][33];
    const int i0 = blockIdx.x * 32;
    const int bx = blockIdx.y * 32;
    const int tx = threadIdx.x, ty = threadIdx.y;  // 32 x 8
#pragma unroll
    for (int r = 0; r < 32; r += 8)
        t[ty + r][tx] = x[(bx + ty + r) * IN_SIZE + i0 + tx];
    __syncthreads();
#pragma unroll
    for (int r = 0; r < 32; r += 8)
        g_xT[(i0 + ty + r) * BATCH + bx + tx] = t[tx][ty + r];

    const int gid = (blockIdx.y * 4 + blockIdx.x) * 256 + ty * 32 + tx;  // 0..32767
    reinterpret_cast<float4*>(out)[gid] = make_float4(0.f, 0.f, 0.f, 0.f);
}

// ---------------- helpers ----------------
__device__ __forceinline__ void sort8(float* v) {
#pragma unroll
    for (int p = 0; p < 8; p++)
#pragma unroll
        for (int k = 0; k < 7; k++)
            if ((k & 1) == (p & 1)) {
                const float lo = fminf(v[k], v[k + 1]);
                const float hi = fmaxf(v[k], v[k + 1]);
                v[k] = lo; v[k + 1] = hi;
            }
}
__device__ __forceinline__ __half hcl(float v) {
    return __float2half(fminf(fmaxf(v, -60000.f), 60000.f));
}

// ---------------- prep: per-interval local tables (1 thread / subnet) -------
__global__ void __launch_bounds__(128) prep_kernel(
    const float* __restrict__ W1, const float* __restrict__ b1,
    const float* __restrict__ W2, const float* __restrict__ b2,
    const float* __restrict__ W3, const float* __restrict__ b3) {
    const int n = blockIdx.x * 128 + threadIdx.x;

    float w1[8], c1[8], c2[8], w3r[8], w2[64];
#pragma unroll
    for (int k = 0; k < 8; k++) {
        w1[k]  = __ldg(W1 + n * 8 + k);
        c1[k]  = __ldg(b1 + n * 8 + k);
        c2[k]  = __ldg(b2 + n * 8 + k);
        w3r[k] = __ldg(W3 + n * 8 + k);
    }
#pragma unroll
    for (int e = 0; e < 64; e++) w2[e] = __ldg(W2 + n * 64 + e);
    const float b3v = __ldg(b3 + n);

    float tau[8];
#pragma unroll
    for (int k = 0; k < 8; k++) {
        float v = __fdividef(-c1[k], w1[k]);
        tau[k] = (fabsf(v) < BIG) ? v : SENT;
    }
    sort8(tau);

    float* dst = g_tab + (size_t)n * TAB;
#pragma unroll
    for (int k = 0; k < 4; k++)
        reinterpret_cast<__half2*>(dst)[k] =
            __halves2half2(hcl(tau[2 * k]), hcl(tau[2 * k + 1]));

#pragma unroll
    for (int s = 0; s < 9; s++) {
        const float loS = (s == 0) ? -SENT : tau[s - 1];
        const float hiS = (s == 8) ?  SENT : tau[s];

        float rep;
        if (s == 0)      rep = (tau[0] >= BIG) ? 0.0f
                                : tau[0] - (1.0f + 0.5f * fabsf(tau[0]));
        else if (s == 8) rep = tau[7] + (1.0f + 0.5f * fabsf(tau[7]));
        else             rep = 0.5f * tau[s - 1] + 0.5f * tau[s];

        // layer-2 affine coefs on this interval (exact, fp32)
        float a[8], bb[8];
#pragma unroll
        for (int j = 0; j < 8; j++) {
            float aa = 0.0f, bs = c2[j];
#pragma unroll
            for (int k = 0; k < 8; k++) {
                const bool act = fmaf(w1[k], rep, c1[k]) > 0.0f;
                aa = fmaf(w2[j * 8 + k], act ? w1[k] : 0.0f, aa);
                bs = fmaf(w2[j * 8 + k], act ? c1[k] : 0.0f, bs);
            }
            a[j] = aa; bb[j] = bs;
        }

        // hinge positions strictly inside (loS, hiS), sorted; pad -> SENT
        float u[8];
#pragma unroll
        for (int j = 0; j < 8; j++) {
            const float uu = __fdividef(-bb[j], a[j]);
            const bool ok = (loS < uu) && (uu < hiS) && (fabsf(uu) < BIG);
            u[j] = ok ? uu : SENT;
        }
        sort8(u);

        float* ib = dst + 4 + 28 * s;
#pragma unroll
        for (int k = 0; k < 4; k++)
            reinterpret_cast<__half2*>(ib)[k] =
                __halves2half2(hcl(u[2 * k]), hcl(u[2 * k + 1]));

        // exact (A,B) per sub-segment rank tt (unreachable slots replicate last)
        float lastA = 0.f, lastB = 0.f;
#pragma unroll
        for (int tt = 0; tt < 9; tt++) {
            const bool valid = (tt == 0) || (u[tt - 1] < BIG);
            if (valid) {
                const float sLo = (tt == 0) ? loS : u[tt - 1];
                const float sHi = (tt < 8 && u[tt] < BIG) ? u[tt] : hiS;
                float rep2;
                if (sLo <= -BIG && sHi >= BIG) rep2 = 0.0f;
                else if (sLo <= -BIG)          rep2 = sHi - (1.0f + 0.5f * fabsf(sHi));
                else if (sHi >= BIG)           rep2 = sLo + (1.0f + 0.5f * fabsf(sLo));
                else                           rep2 = 0.5f * sLo + 0.5f * sHi;

                float A = 0.0f, Bv = b3v;
#pragma unroll
                for (int j = 0; j < 8; j++) {
                    const bool act = fmaf(a[j], rep2, bb[j]) > 0.0f;
                    A  = fmaf(w3r[j], act ? a[j]  : 0.0f, A);
                    Bv = fmaf(w3r[j], act ? bb[j] : 0.0f, Bv);
                }
                lastA = A; lastB = Bv;
            }
            ib[4 + 2 * tt]     = lastA;
            ib[4 + 2 * tt + 1] = lastB;
        }
    }
}

// ---------------- eval ----------------
#define O_PER_CTA 4
#define I_PER_CTA 8
#define SMEM_BYTES (O_PER_CTA * I_PER_CTA * TAB * 4)  // 32768

__device__ __forceinline__ uint4 lds128(uint32_t a) {
    uint4 v;
    asm("ld.shared.v4.u32 {%0,%1,%2,%3}, [%4];"
        : "=r"(v.x), "=r"(v.y), "=r"(v.z), "=r"(v.w) : "r"(a));
    return v;
}
__device__ __forceinline__ float2 lds64f(uint32_t a) {
    float2 v;
    asm("ld.shared.v2.f32 {%0,%1}, [%2];" : "=f"(v.x), "=f"(v.y) : "r"(a));
    return v;
}
__device__ __forceinline__ __half2 u2h(uint32_t u) {
    __half2 h; memcpy(&h, &u, 4); return h;
}
// count of the 8 packed fp16 values (in t) that are < x2 (both halves == x)
__device__ __forceinline__ int count8(__half2 x2, uint4 t) {
    __half2 s = __hadd2(__hadd2(__hgt2(x2, u2h(t.x)), __hgt2(x2, u2h(t.y))),
                        __hadd2(__hgt2(x2, u2h(t.z)), __hgt2(x2, u2h(t.w))));
    return __half2int_rn(__hadd(__low2half(s), __high2half(s)));
}

__global__ void __launch_bounds__(128, 6) eval_kernel(float* __restrict__ out) {
    extern __shared__ float sw[];
    const int obase = blockIdx.x * O_PER_CTA;
    const int bt    = blockIdx.y;
    const int ibase = blockIdx.z * I_PER_CTA;
    const int tid   = threadIdx.x;

    // stage 32 tables (64 float4 each), coalesced
    for (int idx = tid; idx < 32 * 64; idx += 128) {
        const int tI = idx >> 6;
        const int e  = idx & 63;
        const int li = tI >> 2, lo = tI & 3;
        const int nn = ((ibase + li) << 7) + obase + lo;
        reinterpret_cast<float4*>(sw)[idx] =
            __ldg(reinterpret_cast<const float4*>(g_tab + (size_t)nn * TAB) + e);
    }
    __syncthreads();

    const int b0 = bt * 512 + tid * 4;
    const uint32_t a0 = (uint32_t)__cvta_generic_to_shared(sw);
    float4 xv = __ldg(reinterpret_cast<const float4*>(g_xT + ibase * BATCH + b0));

    float acc[O_PER_CTA][4];
#pragma unroll
    for (int lo = 0; lo < O_PER_CTA; lo++)
#pragma unroll
        for (int e = 0; e < 4; e++) acc[lo][e] = 0.f;

    for (int li = 0; li < I_PER_CTA; li++) {
        const int inx = ibase + ((li < I_PER_CTA - 1) ? (li + 1) : li);
        const float4 xnext =
            __ldg(reinterpret_cast<const float4*>(g_xT + inx * BATCH + b0));

        const float xe[4] = {xv.x, xv.y, xv.z, xv.w};
        __half2 xh[4];
#pragma unroll
        for (int e = 0; e < 4; e++) xh[e] = __half2half2(__float2half(xe[e]));

#pragma unroll
        for (int lo = 0; lo < O_PER_CTA; lo++) {
            const uint32_t tb = a0 + (li * 4 + lo) * (TAB * 4);
            const uint4 t4 = lds128(tb);  // 8 thresholds (broadcast)
#pragma unroll
            for (int e = 0; e < 4; e++) {
                const int c = count8(xh[e], t4);
                const uint32_t ibA = tb + 16 + 112 * c;
                const uint4 u4 = lds128(ibA);          // 8 hinge u's (16 B)
                const int r = count8(xh[e], u4);
                const float2 ab = lds64f(ibA + 16 + 8 * r);  // exact (A,B)
                acc[lo][e] = fmaf(ab.x, xe[e], acc[lo][e]) + ab.y;
            }
        }
        xv = xnext;
    }

#pragma unroll
    for (int lo = 0; lo < O_PER_CTA; lo++)
#pragma unroll
        for (int e = 0; e < 4; e++)
            atomicAdd(&out[(b0 + e) * OUT_SIZE + obase + lo], acc[lo][e]);
}

extern "C" void kernel_launch(void* const* d_in, const int* in_sizes, int n_in,
                              void* d_out, int out_size) {
    const float* x  = (const float*)d_in[0];
    const float* W1 = (const float*)d_in[1];
    const float* b1 = (const float*)d_in[2];
    const float* W2 = (const float*)d_in[3];
    const float* b2 = (const float*)d_in[4];
    const float* W3 = (const float*)d_in[5];
    const float* b3 = (const float*)d_in[6];
    float* out = (float*)d_out;

    cudaFuncSetAttribute(eval_kernel, cudaFuncAttributeMaxDynamicSharedMemorySize,
                         SMEM_BYTES);

    xt_kernel<<<dim3(IN_SIZE / 32, BATCH / 32), dim3(32, 8)>>>(x, out);
    prep_kernel<<<N_SUB / 128, 128>>>(W1, b1, W2, b2, W3, b3);
    eval_kernel<<<dim3(OUT_SIZE / O_PER_CTA, 2, IN_SIZE / I_PER_CTA), 128,
                  SMEM_BYTES>>>(out);
}